// round 5
// baseline (speedup 1.0000x reference)
#include <cuda_runtime.h>
#include <cuda_bf16.h>
#include <cstdint>
#include <math.h>

#define BATCH 1280
#define EDIM  512
#define D2    1024
#define D6    3072
#define TV    64
#define BN_EPS 1e-5f

// ---- mma (shadow path) tiling ----
#define BMM 128
#define BNM 64
#define BKM 32
#define ROWB 80              // padded smem row stride bytes (40 bf16)
#define OFF_AHI 0
#define OFF_ALO (BMM * ROWB)
#define OFF_BHI (2 * BMM * ROWB)
#define OFF_BLO (2 * BMM * ROWB + BNM * ROWB)
#define SMEM_BYTES (2 * BMM * ROWB + 2 * BNM * ROWB)

// ---------------- device globals (scratch; zero-initialized) ----------------
__device__ __align__(16) float g_qm[BATCH * D2];
__device__ __align__(16) float g_am[BATCH * D2];
__device__ __align__(16) float g_X [BATCH * D6];
__device__ __align__(16) float g_h_simt[BATCH * EDIM];
__device__ __align__(16) float g_h_mma [BATCH * EDIM];
__device__ __align__(16) float g_h     [BATCH * EDIM];
__device__ __align__(16) __nv_bfloat16 g_X_hi[BATCH * D6], g_X_lo[BATCH * D6];
__device__ __align__(16) __nv_bfloat16 g_Wc1T_hi[EDIM * D6], g_Wc1T_lo[EDIM * D6];
__device__ float g_sum[EDIM], g_sumsq[EDIM], g_wc[EDIM], g_cst[1];

__device__ __forceinline__ void split_store(__nv_bfloat16* hi, __nv_bfloat16* lo,
                                            int idx, float v) {
    __nv_bfloat16 h = __float2bfloat16(v);
    hi[idx] = h;
    lo[idx] = __float2bfloat16(v - __bfloat162float(h));
}

__device__ __forceinline__ void mma_bf16(float* c, const uint32_t* a,
                                         uint32_t b0, uint32_t b1) {
    asm volatile(
        "mma.sync.aligned.m16n8k16.row.col.f32.bf16.bf16.f32 "
        "{%0,%1,%2,%3}, {%4,%5,%6,%7}, {%8,%9}, {%0,%1,%2,%3};"
        : "+f"(c[0]), "+f"(c[1]), "+f"(c[2]), "+f"(c[3])
        : "r"(a[0]), "r"(a[1]), "r"(a[2]), "r"(a[3]), "r"(b0), "r"(b1));
}

// ---------------- zero BN stats ---------------------------------------------
__global__ void zero_stats_kernel() {
    g_sum[threadIdx.x] = 0.f;
    g_sumsq[threadIdx.x] = 0.f;
}

// ---------------- weight transpose + bf16 split (Wc1 only) ------------------
__global__ void wsplit_kernel(const float* __restrict__ W,
                              __nv_bfloat16* __restrict__ oh,
                              __nv_bfloat16* __restrict__ ol, int K) {
    __shared__ float t[32][33];
    const int k0 = blockIdx.x * 32, n0 = blockIdx.y * 32;
    const int tx = threadIdx.x, ty = threadIdx.y;
    for (int i = ty; i < 32; i += 8)
        t[i][tx] = W[(k0 + i) * EDIM + n0 + tx];
    __syncthreads();
    for (int i = ty; i < 32; i += 8)
        split_store(oh, ol, (n0 + i) * K + k0 + tx, t[tx][i]);
}

// ---------------- fused sequence-mean reductions (R1 verbatim) --------------
__global__ void reduce_kernel(const float4* __restrict__ Q,
                              const float4* __restrict__ Vq,
                              const float4* __restrict__ A,
                              const float4* __restrict__ Va,
                              const int* __restrict__ qlen,
                              const int* __restrict__ alen) {
    const int b = blockIdx.x;
    const int which = blockIdx.y;
    const int d4 = threadIdx.x;
    const int stride = BATCH * (D2 / 4);

    const float4* p;
    int L;
    if (which == 0)      { L = max(qlen[b], 1); p = Q  + b * (D2 / 4) + d4; }
    else if (which == 1) { L = TV;              p = Vq + b * (D2 / 4) + d4; }
    else if (which == 2) { L = max(alen[b], 1); p = A  + b * (D2 / 4) + d4; }
    else                 { L = TV;              p = Va + b * (D2 / 4) + d4; }

    float4 acc = make_float4(0.f, 0.f, 0.f, 0.f);
    #pragma unroll 8
    for (int t = 0; t < L; t++) {
        float4 v = p[t * stride];
        acc.x += v.x; acc.y += v.y; acc.z += v.z; acc.w += v.w;
    }
    float inv = 1.f / (float)L;
    acc.x *= inv; acc.y *= inv; acc.z *= inv; acc.w *= inv;

    float4* dst;
    if (which == 0)      dst = (float4*)g_qm + b * (D2 / 4) + d4;
    else if (which == 1) dst = (float4*)g_X  + b * (D6 / 4) + (EDIM / 4) + d4;
    else if (which == 2) dst = (float4*)g_am + b * (D2 / 4) + d4;
    else                 dst = (float4*)g_X  + b * (D6 / 4) + (2048 / 4) + d4;
    *dst = acc;
}

// ---------------- SIMT fp32 GEMM (R1 structure + double buffer/prefetch) ----
template <int MODE>
__global__ __launch_bounds__(256) void sgemm_kernel(const float* __restrict__ W,
                                                    const float* __restrict__ bias) {
    const float* __restrict__ Aptr;
    float* __restrict__ C;
    int lda, ldc, K;
    if (MODE == 0)      { Aptr = g_qm; C = g_X;            lda = D2; ldc = D6;   K = D2; }
    else if (MODE == 1) { Aptr = g_am; C = g_X + 3 * EDIM; lda = D2; ldc = D6;   K = D2; }
    else                { Aptr = g_X;  C = g_h_simt;       lda = D6; ldc = EDIM; K = D6; }

    __shared__ __align__(16) float As[2][16 * 64];   // As[s][k][m]
    __shared__ __align__(16) float Bs[2][16 * 64];   // Bs[s][k][n]

    const int tid = threadIdx.x;
    const int tx = tid & 15, ty = tid >> 4;
    const int bm = blockIdx.y * 64, bn = blockIdx.x * 64;
    const int arow = tid >> 2, ak = (tid & 3) << 2;
    const int brow = tid >> 4, bcol = (tid & 15) << 2;

    const float* Ag = Aptr + (size_t)(bm + arow) * lda + ak;
    const float* Wg = W + (size_t)brow * EDIM + bn + bcol;

    float c[4][4] = {};

    // prologue: chunk 0 -> buffer 0
    float4 av = *(const float4*)(Ag);
    float4 bv = *(const float4*)(Wg);
    As[0][(ak + 0) * 64 + arow] = av.x;
    As[0][(ak + 1) * 64 + arow] = av.y;
    As[0][(ak + 2) * 64 + arow] = av.z;
    As[0][(ak + 3) * 64 + arow] = av.w;
    *(float4*)(&Bs[0][brow * 64 + bcol]) = bv;
    __syncthreads();

    int s = 0;
    for (int k0 = 0; k0 < K; k0 += 16) {
        const bool more = (k0 + 16) < K;
        if (more) {   // issue next-chunk loads early; latency hidden by compute
            av = *(const float4*)(Ag + k0 + 16);
            bv = *(const float4*)(Wg + (size_t)(k0 + 16) * EDIM);
        }
        #pragma unroll
        for (int k = 0; k < 16; k++) {
            float4 a = *(const float4*)(&As[s][k * 64 + ty * 4]);
            float4 b = *(const float4*)(&Bs[s][k * 64 + tx * 4]);
            c[0][0] += a.x * b.x; c[0][1] += a.x * b.y; c[0][2] += a.x * b.z; c[0][3] += a.x * b.w;
            c[1][0] += a.y * b.x; c[1][1] += a.y * b.y; c[1][2] += a.y * b.z; c[1][3] += a.y * b.w;
            c[2][0] += a.z * b.x; c[2][1] += a.z * b.y; c[2][2] += a.z * b.z; c[2][3] += a.z * b.w;
            c[3][0] += a.w * b.x; c[3][1] += a.w * b.y; c[3][2] += a.w * b.z; c[3][3] += a.w * b.w;
        }
        if (more) {   // fill other buffer while this one was being read
            As[s ^ 1][(ak + 0) * 64 + arow] = av.x;
            As[s ^ 1][(ak + 1) * 64 + arow] = av.y;
            As[s ^ 1][(ak + 2) * 64 + arow] = av.z;
            As[s ^ 1][(ak + 3) * 64 + arow] = av.w;
            *(float4*)(&Bs[s ^ 1][brow * 64 + bcol]) = bv;
        }
        __syncthreads();
        s ^= 1;
    }

    #pragma unroll
    for (int i = 0; i < 4; i++) {
        int row = bm + ty * 4 + i;
        #pragma unroll
        for (int j = 0; j < 4; j++) {
            int col = bn + tx * 4 + j;
            float v = c[i][j] + bias[col];
            if (MODE == 2) v = (v > 0.f) ? v : expm1f(v);
            C[(size_t)row * ldc + col] = v;
        }
    }
}

// ---------------- X float -> bf16 hi/lo split -------------------------------
__global__ void xsplit_kernel() {
    const int i4 = blockIdx.x * 256 + threadIdx.x;    // float4 index
    float4 v = ((const float4*)g_X)[i4];
    const int b = i4 * 4;
    split_store(g_X_hi, g_X_lo, b + 0, v.x);
    split_store(g_X_hi, g_X_lo, b + 1, v.y);
    split_store(g_X_hi, g_X_lo, b + 2, v.z);
    split_store(g_X_hi, g_X_lo, b + 3, v.w);
}

// ---------------- shadow big GEMM via mma.sync (split bf16) -----------------
__global__ __launch_bounds__(256)
void gemm_mma_big(const float* __restrict__ bias) {
    __shared__ __align__(16) unsigned char smem[SMEM_BYTES];

    const int tid = threadIdx.x;
    const int w = tid >> 5, l = tid & 31;
    const int wm = w & 3, wn = w >> 2;
    const int g = l >> 2, tg = l & 3;

    const int Ktot = D6;
    const int bm = blockIdx.y * BMM, bn = blockIdx.x * BNM;
    const int ldv = Ktot >> 3;
    const uint4* gAhi = (const uint4*)g_X_hi + (size_t)bm * ldv;
    const uint4* gAlo = (const uint4*)g_X_lo + (size_t)bm * ldv;
    const uint4* gBhi = (const uint4*)g_Wc1T_hi + (size_t)bn * ldv;
    const uint4* gBlo = (const uint4*)g_Wc1T_lo + (size_t)bn * ldv;

    const int ar0 = tid >> 2, as0 = tid & 3;
    const int ar1 = ar0 + 64;

    const unsigned char* saH = smem + OFF_AHI + (wm * 32 + g) * ROWB + tg * 4;
    const unsigned char* saL = smem + OFF_ALO + (wm * 32 + g) * ROWB + tg * 4;
    const unsigned char* sbH = smem + OFF_BHI + (wn * 32 + g) * ROWB + tg * 4;
    const unsigned char* sbL = smem + OFF_BLO + (wn * 32 + g) * ROWB + tg * 4;

    float c[2][4][4] = {};

    const int niter = Ktot / BKM;
    uint4 pAh0 = gAhi[ar0 * ldv + as0], pAl0 = gAlo[ar0 * ldv + as0];
    uint4 pAh1 = gAhi[ar1 * ldv + as0], pAl1 = gAlo[ar1 * ldv + as0];
    uint4 pBh  = gBhi[ar0 * ldv + as0], pBl  = gBlo[ar0 * ldv + as0];

    for (int it = 0; it < niter; it++) {
        __syncthreads();
        *(uint4*)(smem + OFF_AHI + ar0 * ROWB + as0 * 16) = pAh0;
        *(uint4*)(smem + OFF_ALO + ar0 * ROWB + as0 * 16) = pAl0;
        *(uint4*)(smem + OFF_AHI + ar1 * ROWB + as0 * 16) = pAh1;
        *(uint4*)(smem + OFF_ALO + ar1 * ROWB + as0 * 16) = pAl1;
        *(uint4*)(smem + OFF_BHI + ar0 * ROWB + as0 * 16) = pBh;
        *(uint4*)(smem + OFF_BLO + ar0 * ROWB + as0 * 16) = pBl;
        __syncthreads();

        if (it + 1 < niter) {
            const int kv = (it + 1) * (BKM / 8);
            pAh0 = gAhi[ar0 * ldv + kv + as0]; pAl0 = gAlo[ar0 * ldv + kv + as0];
            pAh1 = gAhi[ar1 * ldv + kv + as0]; pAl1 = gAlo[ar1 * ldv + kv + as0];
            pBh  = gBhi[ar0 * ldv + kv + as0]; pBl  = gBlo[ar0 * ldv + kv + as0];
        }

        #pragma unroll
        for (int ks = 0; ks < 2; ks++) {
            const int kb = ks * 32;
            uint32_t ah[2][4], al[2][4];
            #pragma unroll
            for (int mt = 0; mt < 2; mt++) {
                const unsigned char* pH = saH + mt * (16 * ROWB) + kb;
                const unsigned char* pL = saL + mt * (16 * ROWB) + kb;
                ah[mt][0] = *(const uint32_t*)(pH);
                ah[mt][1] = *(const uint32_t*)(pH + 8 * ROWB);
                ah[mt][2] = *(const uint32_t*)(pH + 16);
                ah[mt][3] = *(const uint32_t*)(pH + 8 * ROWB + 16);
                al[mt][0] = *(const uint32_t*)(pL);
                al[mt][1] = *(const uint32_t*)(pL + 8 * ROWB);
                al[mt][2] = *(const uint32_t*)(pL + 16);
                al[mt][3] = *(const uint32_t*)(pL + 8 * ROWB + 16);
            }
            uint32_t bh[2][2][2], bl[2][2][2];
            #pragma unroll
            for (int np = 0; np < 2; np++)
                #pragma unroll
                for (int h = 0; h < 2; h++) {
                    const unsigned char* pH = sbH + (np * 16 + h * 8) * ROWB + kb;
                    const unsigned char* pL = sbL + (np * 16 + h * 8) * ROWB + kb;
                    bh[np][h][0] = *(const uint32_t*)(pH);
                    bh[np][h][1] = *(const uint32_t*)(pH + 16);
                    bl[np][h][0] = *(const uint32_t*)(pL);
                    bl[np][h][1] = *(const uint32_t*)(pL + 16);
                }
            #pragma unroll
            for (int mt = 0; mt < 2; mt++)
                #pragma unroll
                for (int np = 0; np < 2; np++)
                    #pragma unroll
                    for (int h = 0; h < 2; h++) {
                        float* acc = c[mt][np * 2 + h];
                        mma_bf16(acc, ah[mt], bh[np][h][0], bh[np][h][1]);
                        mma_bf16(acc, al[mt], bh[np][h][0], bh[np][h][1]);
                        mma_bf16(acc, ah[mt], bl[np][h][0], bl[np][h][1]);
                    }
        }
    }

    #pragma unroll
    for (int mt = 0; mt < 2; mt++) {
        #pragma unroll
        for (int nt = 0; nt < 4; nt++) {
            const int col = bn + wn * 32 + nt * 8 + tg * 2;
            const float b0v = bias[col], b1v = bias[col + 1];
            const int r0 = bm + wm * 32 + mt * 16 + g;
            float v00 = c[mt][nt][0] + b0v;
            float v01 = c[mt][nt][1] + b1v;
            float v10 = c[mt][nt][2] + b0v;
            float v11 = c[mt][nt][3] + b1v;
            if (v00 <= 0.f) v00 = expm1f(v00);
            if (v01 <= 0.f) v01 = expm1f(v01);
            if (v10 <= 0.f) v10 = expm1f(v10);
            if (v11 <= 0.f) v11 = expm1f(v11);
            g_h_mma[(size_t)r0 * EDIM + col]           = v00;
            g_h_mma[(size_t)r0 * EDIM + col + 1]       = v01;
            g_h_mma[(size_t)(r0 + 8) * EDIM + col]     = v10;
            g_h_mma[(size_t)(r0 + 8) * EDIM + col + 1] = v11;
        }
    }
}

// ---------------- verified select: use mma only if whole block agrees -------
__global__ void select_kernel() {
    const int i = blockIdx.x * 256 + threadIdx.x;
    const float s = g_h_simt[i], m = g_h_mma[i];
    const float d = fabsf(m - s);
    const int ok = (d <= 5e-3f * (fabsf(s) + 1.0f)) ? 1 : 0;
    const int all = __syncthreads_and(ok);
    g_h[i] = all ? m : s;
}

// ---------------- BN batch stats --------------------------------------------
__global__ void bn_stats_kernel() {
    const int r0 = blockIdx.x * 64;
    for (int c = threadIdx.x; c < EDIM; c += blockDim.x) {
        float s = 0.f, s2 = 0.f;
        #pragma unroll 8
        for (int r = 0; r < 64; r++) {
            float v = g_h[(r0 + r) * EDIM + c];
            s += v; s2 += v * v;
        }
        atomicAdd(&g_sum[c], s);
        atomicAdd(&g_sumsq[c], s2);
    }
}

// ---------------- fold BN + Wc2 ---------------------------------------------
__global__ void bn_finalize_kernel(const float* __restrict__ gamma,
                                   const float* __restrict__ beta,
                                   const float* __restrict__ Wc2,
                                   const float* __restrict__ bc2) {
    __shared__ float red[EDIM];
    const int c = threadIdx.x;
    const float invB = 1.f / (float)BATCH;
    float mu  = g_sum[c] * invB;
    float var = fmaxf(g_sumsq[c] * invB - mu * mu, 0.f);
    float s   = gamma[c] * rsqrtf(var + BN_EPS);
    float w2  = Wc2[c];
    g_wc[c]   = s * w2;
    red[c]    = (beta[c] - mu * s) * w2;
    __syncthreads();
    for (int off = EDIM / 2; off > 0; off >>= 1) {
        if (c < off) red[c] += red[c + off];
        __syncthreads();
    }
    if (c == 0) g_cst[0] = red[0] + bc2[0];
}

// ---------------- final GEMV ------------------------------------------------
__global__ void gemv_kernel(float* __restrict__ out) {
    const int warp = threadIdx.x >> 5;
    const int lane = threadIdx.x & 31;
    const int b = blockIdx.x * 8 + warp;
    const float* hr = g_h + (size_t)b * EDIM;
    float s = 0.f;
    #pragma unroll
    for (int c = lane; c < EDIM; c += 32) s += hr[c] * g_wc[c];
    #pragma unroll
    for (int off = 16; off > 0; off >>= 1) s += __shfl_down_sync(0xffffffffu, s, off);
    if (lane == 0) out[b] = s + g_cst[0];
}

// ---------------- launcher --------------------------------------------------
extern "C" void kernel_launch(void* const* d_in, const int* in_sizes, int n_in,
                              void* d_out, int out_size) {
    const float* Q    = (const float*)d_in[0];
    const float* Vq   = (const float*)d_in[1];
    const float* Aa   = (const float*)d_in[2];
    const float* Va   = (const float*)d_in[3];
    const int*   qlen = (const int*)d_in[4];
    const int*   alen = (const int*)d_in[5];
    const float* Wq   = (const float*)d_in[6];
    const float* bq   = (const float*)d_in[7];
    const float* Wa   = (const float*)d_in[8];
    const float* ba   = (const float*)d_in[9];
    const float* Wc1  = (const float*)d_in[10];
    const float* bc1  = (const float*)d_in[11];
    const float* gam  = (const float*)d_in[12];
    const float* bet  = (const float*)d_in[13];
    const float* Wc2  = (const float*)d_in[14];
    const float* bc2  = (const float*)d_in[15];
    float* out = (float*)d_out;

    zero_stats_kernel<<<1, EDIM>>>();
    wsplit_kernel<<<dim3(D6 / 32, EDIM / 32), dim3(32, 8)>>>(Wc1, g_Wc1T_hi, g_Wc1T_lo, D6);
    reduce_kernel<<<dim3(BATCH, 4), 256>>>((const float4*)Q, (const float4*)Vq,
                                           (const float4*)Aa, (const float4*)Va,
                                           qlen, alen);
    sgemm_kernel<0><<<dim3(8, 20), 256>>>(Wq, bq);
    sgemm_kernel<1><<<dim3(8, 20), 256>>>(Wa, ba);
    sgemm_kernel<2><<<dim3(8, 20), 256>>>(Wc1, bc1);
    xsplit_kernel<<<BATCH * D6 / 4 / 256, 256>>>();
    gemm_mma_big<<<dim3(EDIM / BNM, BATCH / BMM), 256>>>(bc1);
    select_kernel<<<BATCH * EDIM / 256, 256>>>();
    bn_stats_kernel<<<BATCH / 64, 256>>>();
    bn_finalize_kernel<<<1, EDIM>>>(gam, bet, Wc2, bc2);
    gemv_kernel<<<BATCH / 8, 256>>>(out);
}

// round 7
// speedup vs baseline: 1.9118x; 1.9118x over previous
#include <cuda_runtime.h>
#include <cuda_bf16.h>
#include <cstdint>
#include <math.h>

#define BATCH 1280
#define EDIM  512
#define D2    1024
#define D6    3072
#define TV    64
#define BN_EPS 1e-5f

// ---- mma tiling ----
#define BMM 128
#define BNM 64
#define BKM 32
#define ROWB 80              // padded smem row stride bytes (40 bf16)
#define OFF_AHI 0
#define OFF_ALO (BMM * ROWB)
#define OFF_BHI (2 * BMM * ROWB)
#define OFF_BLO (2 * BMM * ROWB + BNM * ROWB)
#define SMEM_BYTES (2 * BMM * ROWB + 2 * BNM * ROWB)

// ---------------- device globals (scratch; zero-initialized) ----------------
__device__ __align__(16) float g_qm[BATCH * D2];
__device__ __align__(16) float g_am[BATCH * D2];
__device__ __align__(16) float g_X [BATCH * D6];
__device__ __align__(16) float g_h [BATCH * EDIM];
__device__ __align__(16) __nv_bfloat16 g_qm_hi[BATCH * D2], g_qm_lo[BATCH * D2];
__device__ __align__(16) __nv_bfloat16 g_am_hi[BATCH * D2], g_am_lo[BATCH * D2];
__device__ __align__(16) __nv_bfloat16 g_X_hi[BATCH * D6],  g_X_lo[BATCH * D6];
__device__ __align__(16) __nv_bfloat16 g_WqT_hi[EDIM * D2],  g_WqT_lo[EDIM * D2];
__device__ __align__(16) __nv_bfloat16 g_WaT_hi[EDIM * D2],  g_WaT_lo[EDIM * D2];
__device__ __align__(16) __nv_bfloat16 g_Wc1T_hi[EDIM * D6], g_Wc1T_lo[EDIM * D6];
__device__ float g_sum[EDIM], g_sumsq[EDIM], g_wc[EDIM], g_cst[1];

__device__ __forceinline__ void split_store(__nv_bfloat16* hi, __nv_bfloat16* lo,
                                            int idx, float v) {
    __nv_bfloat16 h = __float2bfloat16(v);
    hi[idx] = h;
    lo[idx] = __float2bfloat16(v - __bfloat162float(h));
}

__device__ __forceinline__ void mma_bf16(float* c, const uint32_t* a,
                                         uint32_t b0, uint32_t b1) {
    asm volatile(
        "mma.sync.aligned.m16n8k16.row.col.f32.bf16.bf16.f32 "
        "{%0,%1,%2,%3}, {%4,%5,%6,%7}, {%8,%9}, {%0,%1,%2,%3};"
        : "+f"(c[0]), "+f"(c[1]), "+f"(c[2]), "+f"(c[3])
        : "r"(a[0]), "r"(a[1]), "r"(a[2]), "r"(a[3]), "r"(b0), "r"(b1));
}

// ---------------- zero BN stats ---------------------------------------------
__global__ void zero_stats_kernel() {
    g_sum[threadIdx.x] = 0.f;
    g_sumsq[threadIdx.x] = 0.f;
}

// ---------------- weight transpose + bf16 split -----------------------------
// W [K, 512] fp32 -> out [512, K] bf16 hi/lo.
// Output pointers resolved IN DEVICE CODE (which: 0=Wq, 1=Wa, 2=Wc1) — passing
// __device__ globals as host-side kernel args silently targets the host shadow
// symbol on GB300 (ATS), leaving the device arrays zero. That was the R3-R6 bug.
__global__ void wsplit_kernel(const float* __restrict__ W, int which, int K) {
    __nv_bfloat16 *oh, *ol;
    if (which == 0)      { oh = g_WqT_hi;  ol = g_WqT_lo;  }
    else if (which == 1) { oh = g_WaT_hi;  ol = g_WaT_lo;  }
    else                 { oh = g_Wc1T_hi; ol = g_Wc1T_lo; }
    __shared__ float t[32][33];
    const int k0 = blockIdx.x * 32, n0 = blockIdx.y * 32;
    const int tx = threadIdx.x, ty = threadIdx.y;
    for (int i = ty; i < 32; i += 8)
        t[i][tx] = W[(k0 + i) * EDIM + n0 + tx];
    __syncthreads();
    for (int i = ty; i < 32; i += 8)
        split_store(oh, ol, (n0 + i) * K + k0 + tx, t[tx][i]);
}

// ---------------- fused sequence-mean reductions (fp32; verified R1/R5) -----
__global__ void reduce_kernel(const float4* __restrict__ Q,
                              const float4* __restrict__ Vq,
                              const float4* __restrict__ A,
                              const float4* __restrict__ Va,
                              const int* __restrict__ qlen,
                              const int* __restrict__ alen) {
    const int b = blockIdx.x;
    const int which = blockIdx.y;
    const int d4 = threadIdx.x;
    const int stride = BATCH * (D2 / 4);

    const float4* p;
    int L;
    if (which == 0)      { L = max(qlen[b], 1); p = Q  + b * (D2 / 4) + d4; }
    else if (which == 1) { L = TV;              p = Vq + b * (D2 / 4) + d4; }
    else if (which == 2) { L = max(alen[b], 1); p = A  + b * (D2 / 4) + d4; }
    else                 { L = TV;              p = Va + b * (D2 / 4) + d4; }

    float4 acc = make_float4(0.f, 0.f, 0.f, 0.f);
    #pragma unroll 8
    for (int t = 0; t < L; t++) {
        float4 v = p[t * stride];
        acc.x += v.x; acc.y += v.y; acc.z += v.z; acc.w += v.w;
    }
    float inv = 1.f / (float)L;
    acc.x *= inv; acc.y *= inv; acc.z *= inv; acc.w *= inv;

    float4* dst;
    if (which == 0)      dst = (float4*)g_qm + b * (D2 / 4) + d4;
    else if (which == 1) dst = (float4*)g_X  + b * (D6 / 4) + (EDIM / 4) + d4;
    else if (which == 2) dst = (float4*)g_am + b * (D2 / 4) + d4;
    else                 dst = (float4*)g_X  + b * (D6 / 4) + (2048 / 4) + d4;
    *dst = acc;
}

// ---------------- fp32 -> bf16 hi/lo split ----------------------------------
// which: 0 -> g_qm, 1 -> g_am, 2 -> g_X  (pointers resolved in device code)
__global__ void split_kernel(int which) {
    const int i4 = blockIdx.x * 256 + threadIdx.x;
    const float4* src;
    __nv_bfloat16 *hi, *lo;
    if (which == 0)      { src = (const float4*)g_qm; hi = g_qm_hi; lo = g_qm_lo; }
    else if (which == 1) { src = (const float4*)g_am; hi = g_am_hi; lo = g_am_lo; }
    else                 { src = (const float4*)g_X;  hi = g_X_hi;  lo = g_X_lo;  }
    float4 v = src[i4];
    const int b = i4 * 4;
    split_store(hi, lo, b + 0, v.x);
    split_store(hi, lo, b + 1, v.y);
    split_store(hi, lo, b + 2, v.z);
    split_store(hi, lo, b + 3, v.w);
}

// ---------------- split-bf16 GEMM via mma.sync ------------------------------
// MODE 0: qm @ WqT  -> g_X cols [0,512)       (fp32 store)
// MODE 1: am @ WaT  -> g_X cols [1536,2048)   (fp32 store)
// MODE 2: X @ Wc1T + ELU -> g_h               (fp32 store)
template <int MODE>
__global__ __launch_bounds__(256)
void gemm_mma(const float* __restrict__ bias) {
    __shared__ __align__(16) unsigned char smem[SMEM_BYTES];

    const int tid = threadIdx.x;
    const int w = tid >> 5, l = tid & 31;
    const int wm = w & 3, wn = w >> 2;
    const int g = l >> 2, tg = l & 3;

    const __nv_bfloat16 *Ahi, *Alo, *Bhi, *Blo;
    int Ktot, colbase;
    if (MODE == 0)      { Ahi = g_qm_hi; Alo = g_qm_lo; Bhi = g_WqT_hi;  Blo = g_WqT_lo;  Ktot = D2; colbase = 0; }
    else if (MODE == 1) { Ahi = g_am_hi; Alo = g_am_lo; Bhi = g_WaT_hi;  Blo = g_WaT_lo;  Ktot = D2; colbase = 3 * EDIM; }
    else                { Ahi = g_X_hi;  Alo = g_X_lo;  Bhi = g_Wc1T_hi; Blo = g_Wc1T_lo; Ktot = D6; colbase = 0; }

    const int bm = blockIdx.y * BMM, bn = blockIdx.x * BNM;
    const int ldv = Ktot >> 3;
    const uint4* gAhi = (const uint4*)Ahi + (size_t)bm * ldv;
    const uint4* gAlo = (const uint4*)Alo + (size_t)bm * ldv;
    const uint4* gBhi = (const uint4*)Bhi + (size_t)bn * ldv;
    const uint4* gBlo = (const uint4*)Blo + (size_t)bn * ldv;

    const int ar0 = tid >> 2, as0 = tid & 3;
    const int ar1 = ar0 + 64;

    const unsigned char* saH = smem + OFF_AHI + (wm * 32 + g) * ROWB + tg * 4;
    const unsigned char* saL = smem + OFF_ALO + (wm * 32 + g) * ROWB + tg * 4;
    const unsigned char* sbH = smem + OFF_BHI + (wn * 32 + g) * ROWB + tg * 4;
    const unsigned char* sbL = smem + OFF_BLO + (wn * 32 + g) * ROWB + tg * 4;

    float c[2][4][4] = {};

    const int niter = Ktot / BKM;
    uint4 pAh0 = gAhi[ar0 * ldv + as0], pAl0 = gAlo[ar0 * ldv + as0];
    uint4 pAh1 = gAhi[ar1 * ldv + as0], pAl1 = gAlo[ar1 * ldv + as0];
    uint4 pBh  = gBhi[ar0 * ldv + as0], pBl  = gBlo[ar0 * ldv + as0];

    for (int it = 0; it < niter; it++) {
        __syncthreads();
        *(uint4*)(smem + OFF_AHI + ar0 * ROWB + as0 * 16) = pAh0;
        *(uint4*)(smem + OFF_ALO + ar0 * ROWB + as0 * 16) = pAl0;
        *(uint4*)(smem + OFF_AHI + ar1 * ROWB + as0 * 16) = pAh1;
        *(uint4*)(smem + OFF_ALO + ar1 * ROWB + as0 * 16) = pAl1;
        *(uint4*)(smem + OFF_BHI + ar0 * ROWB + as0 * 16) = pBh;
        *(uint4*)(smem + OFF_BLO + ar0 * ROWB + as0 * 16) = pBl;
        __syncthreads();

        if (it + 1 < niter) {
            const int kv = (it + 1) * (BKM / 8);
            pAh0 = gAhi[ar0 * ldv + kv + as0]; pAl0 = gAlo[ar0 * ldv + kv + as0];
            pAh1 = gAhi[ar1 * ldv + kv + as0]; pAl1 = gAlo[ar1 * ldv + kv + as0];
            pBh  = gBhi[ar0 * ldv + kv + as0]; pBl  = gBlo[ar0 * ldv + kv + as0];
        }

        #pragma unroll
        for (int ks = 0; ks < 2; ks++) {
            const int kb = ks * 32;
            uint32_t ah[2][4], al[2][4];
            #pragma unroll
            for (int mt = 0; mt < 2; mt++) {
                const unsigned char* pH = saH + mt * (16 * ROWB) + kb;
                const unsigned char* pL = saL + mt * (16 * ROWB) + kb;
                ah[mt][0] = *(const uint32_t*)(pH);
                ah[mt][1] = *(const uint32_t*)(pH + 8 * ROWB);
                ah[mt][2] = *(const uint32_t*)(pH + 16);
                ah[mt][3] = *(const uint32_t*)(pH + 8 * ROWB + 16);
                al[mt][0] = *(const uint32_t*)(pL);
                al[mt][1] = *(const uint32_t*)(pL + 8 * ROWB);
                al[mt][2] = *(const uint32_t*)(pL + 16);
                al[mt][3] = *(const uint32_t*)(pL + 8 * ROWB + 16);
            }
            uint32_t bh[2][2][2], bl[2][2][2];
            #pragma unroll
            for (int np = 0; np < 2; np++)
                #pragma unroll
                for (int h = 0; h < 2; h++) {
                    const unsigned char* pH = sbH + (np * 16 + h * 8) * ROWB + kb;
                    const unsigned char* pL = sbL + (np * 16 + h * 8) * ROWB + kb;
                    bh[np][h][0] = *(const uint32_t*)(pH);
                    bh[np][h][1] = *(const uint32_t*)(pH + 16);
                    bl[np][h][0] = *(const uint32_t*)(pL);
                    bl[np][h][1] = *(const uint32_t*)(pL + 16);
                }
            #pragma unroll
            for (int mt = 0; mt < 2; mt++)
                #pragma unroll
                for (int np = 0; np < 2; np++)
                    #pragma unroll
                    for (int h = 0; h < 2; h++) {
                        float* acc = c[mt][np * 2 + h];
                        mma_bf16(acc, ah[mt], bh[np][h][0], bh[np][h][1]);
                        mma_bf16(acc, al[mt], bh[np][h][0], bh[np][h][1]);
                        mma_bf16(acc, ah[mt], bl[np][h][0], bl[np][h][1]);
                    }
        }
    }

    #pragma unroll
    for (int mt = 0; mt < 2; mt++) {
        #pragma unroll
        for (int nt = 0; nt < 4; nt++) {
            const int col = bn + wn * 32 + nt * 8 + tg * 2;
            const float b0v = bias[col], b1v = bias[col + 1];
            const int r0 = bm + wm * 32 + mt * 16 + g;
            float v00 = c[mt][nt][0] + b0v;
            float v01 = c[mt][nt][1] + b1v;
            float v10 = c[mt][nt][2] + b0v;
            float v11 = c[mt][nt][3] + b1v;
            if (MODE == 2) {
                if (v00 <= 0.f) v00 = expm1f(v00);
                if (v01 <= 0.f) v01 = expm1f(v01);
                if (v10 <= 0.f) v10 = expm1f(v10);
                if (v11 <= 0.f) v11 = expm1f(v11);
                g_h[(size_t)r0 * EDIM + col]           = v00;
                g_h[(size_t)r0 * EDIM + col + 1]       = v01;
                g_h[(size_t)(r0 + 8) * EDIM + col]     = v10;
                g_h[(size_t)(r0 + 8) * EDIM + col + 1] = v11;
            } else {
                g_X[(size_t)r0 * D6 + colbase + col]           = v00;
                g_X[(size_t)r0 * D6 + colbase + col + 1]       = v01;
                g_X[(size_t)(r0 + 8) * D6 + colbase + col]     = v10;
                g_X[(size_t)(r0 + 8) * D6 + colbase + col + 1] = v11;
            }
        }
    }
}

// ---------------- BN batch stats --------------------------------------------
__global__ void bn_stats_kernel() {
    const int r0 = blockIdx.x * 64;
    for (int c = threadIdx.x; c < EDIM; c += blockDim.x) {
        float s = 0.f, s2 = 0.f;
        #pragma unroll 8
        for (int r = 0; r < 64; r++) {
            float v = g_h[(r0 + r) * EDIM + c];
            s += v; s2 += v * v;
        }
        atomicAdd(&g_sum[c], s);
        atomicAdd(&g_sumsq[c], s2);
    }
}

// ---------------- fold BN + Wc2 ---------------------------------------------
__global__ void bn_finalize_kernel(const float* __restrict__ gamma,
                                   const float* __restrict__ beta,
                                   const float* __restrict__ Wc2,
                                   const float* __restrict__ bc2) {
    __shared__ float red[EDIM];
    const int c = threadIdx.x;
    const float invB = 1.f / (float)BATCH;
    float mu  = g_sum[c] * invB;
    float var = fmaxf(g_sumsq[c] * invB - mu * mu, 0.f);
    float s   = gamma[c] * rsqrtf(var + BN_EPS);
    float w2  = Wc2[c];
    g_wc[c]   = s * w2;
    red[c]    = (beta[c] - mu * s) * w2;
    __syncthreads();
    for (int off = EDIM / 2; off > 0; off >>= 1) {
        if (c < off) red[c] += red[c + off];
        __syncthreads();
    }
    if (c == 0) g_cst[0] = red[0] + bc2[0];
}

// ---------------- final GEMV ------------------------------------------------
__global__ void gemv_kernel(float* __restrict__ out) {
    const int warp = threadIdx.x >> 5;
    const int lane = threadIdx.x & 31;
    const int b = blockIdx.x * 8 + warp;
    const float* hr = g_h + (size_t)b * EDIM;
    float s = 0.f;
    #pragma unroll
    for (int c = lane; c < EDIM; c += 32) s += hr[c] * g_wc[c];
    #pragma unroll
    for (int off = 16; off > 0; off >>= 1) s += __shfl_down_sync(0xffffffffu, s, off);
    if (lane == 0) out[b] = s + g_cst[0];
}

// ---------------- launcher --------------------------------------------------
extern "C" void kernel_launch(void* const* d_in, const int* in_sizes, int n_in,
                              void* d_out, int out_size) {
    const float* Q    = (const float*)d_in[0];
    const float* Vq   = (const float*)d_in[1];
    const float* Aa   = (const float*)d_in[2];
    const float* Va   = (const float*)d_in[3];
    const int*   qlen = (const int*)d_in[4];
    const int*   alen = (const int*)d_in[5];
    const float* Wq   = (const float*)d_in[6];
    const float* bq   = (const float*)d_in[7];
    const float* Wa   = (const float*)d_in[8];
    const float* ba   = (const float*)d_in[9];
    const float* Wc1  = (const float*)d_in[10];
    const float* bc1  = (const float*)d_in[11];
    const float* gam  = (const float*)d_in[12];
    const float* bet  = (const float*)d_in[13];
    const float* Wc2  = (const float*)d_in[14];
    const float* bc2  = (const float*)d_in[15];
    float* out = (float*)d_out;

    zero_stats_kernel<<<1, EDIM>>>();
    wsplit_kernel<<<dim3(D2 / 32, EDIM / 32), dim3(32, 8)>>>(Wq, 0, D2);
    wsplit_kernel<<<dim3(D2 / 32, EDIM / 32), dim3(32, 8)>>>(Wa, 1, D2);
    wsplit_kernel<<<dim3(D6 / 32, EDIM / 32), dim3(32, 8)>>>(Wc1, 2, D6);
    reduce_kernel<<<dim3(BATCH, 4), 256>>>((const float4*)Q, (const float4*)Vq,
                                           (const float4*)Aa, (const float4*)Va,
                                           qlen, alen);
    split_kernel<<<BATCH * D2 / 1024, 256>>>(0);
    split_kernel<<<BATCH * D2 / 1024, 256>>>(1);
    gemm_mma<0><<<dim3(EDIM / BNM, BATCH / BMM), 256>>>(bq);
    gemm_mma<1><<<dim3(EDIM / BNM, BATCH / BMM), 256>>>(ba);
    split_kernel<<<BATCH * D6 / 1024, 256>>>(2);
    gemm_mma<2><<<dim3(EDIM / BNM, BATCH / BMM), 256>>>(bc1);
    bn_stats_kernel<<<BATCH / 64, 256>>>();
    bn_finalize_kernel<<<1, EDIM>>>(gam, bet, Wc2, bc2);
    gemv_kernel<<<BATCH / 8, 256>>>(out);
}

// round 8
// speedup vs baseline: 2.1180x; 1.1078x over previous
#include <cuda_runtime.h>
#include <cuda_bf16.h>
#include <cstdint>
#include <math.h>

#define BATCH 1280
#define EDIM  512
#define D2    1024
#define D6    3072
#define TV    64
#define BN_EPS 1e-5f

#define ROWB 80              // padded smem row stride bytes (40 bf16)

// ---------------- device globals (scratch; zero-initialized) ----------------
__device__ __align__(16) float g_h [BATCH * EDIM];
__device__ __align__(16) __nv_bfloat16 g_qm_hi[BATCH * D2], g_qm_lo[BATCH * D2];
__device__ __align__(16) __nv_bfloat16 g_am_hi[BATCH * D2], g_am_lo[BATCH * D2];
__device__ __align__(16) __nv_bfloat16 g_X_hi[BATCH * D6],  g_X_lo[BATCH * D6];
__device__ __align__(16) __nv_bfloat16 g_WqT_hi[EDIM * D2],  g_WqT_lo[EDIM * D2];
__device__ __align__(16) __nv_bfloat16 g_WaT_hi[EDIM * D2],  g_WaT_lo[EDIM * D2];
__device__ __align__(16) __nv_bfloat16 g_Wc1T_hi[EDIM * D6], g_Wc1T_lo[EDIM * D6];
__device__ float g_sum[EDIM], g_sumsq[EDIM], g_wc[EDIM], g_cst[1];

__device__ __forceinline__ void split_store(__nv_bfloat16* hi, __nv_bfloat16* lo,
                                            size_t idx, float v) {
    __nv_bfloat16 h = __float2bfloat16(v);
    hi[idx] = h;
    lo[idx] = __float2bfloat16(v - __bfloat162float(h));
}

__device__ __forceinline__ uint32_t smem_u32(const void* p) {
    uint32_t a;
    asm("{ .reg .u64 t; cvta.to.shared.u64 t, %1; cvt.u32.u64 %0, t; }"
        : "=r"(a) : "l"(p));
    return a;
}

__device__ __forceinline__ void ldmat4(uint32_t* r, uint32_t addr) {
    asm volatile("ldmatrix.sync.aligned.m8n8.x4.shared.b16 {%0,%1,%2,%3}, [%4];"
                 : "=r"(r[0]), "=r"(r[1]), "=r"(r[2]), "=r"(r[3]) : "r"(addr));
}

__device__ __forceinline__ void mma_bf16(float* c, const uint32_t* a,
                                         uint32_t b0, uint32_t b1) {
    asm volatile(
        "mma.sync.aligned.m16n8k16.row.col.f32.bf16.bf16.f32 "
        "{%0,%1,%2,%3}, {%4,%5,%6,%7}, {%8,%9}, {%0,%1,%2,%3};"
        : "+f"(c[0]), "+f"(c[1]), "+f"(c[2]), "+f"(c[3])
        : "r"(a[0]), "r"(a[1]), "r"(a[2]), "r"(a[3]), "r"(b0), "r"(b1));
}

// ---------------- zero BN stats ---------------------------------------------
__global__ void zero_stats_kernel() {
    g_sum[threadIdx.x] = 0.f;
    g_sumsq[threadIdx.x] = 0.f;
}

// ---------------- weight transpose + bf16 split (device-resolved outputs) ---
__global__ void wsplit_kernel(const float* __restrict__ W, int which, int K) {
    __nv_bfloat16 *oh, *ol;
    if (which == 0)      { oh = g_WqT_hi;  ol = g_WqT_lo;  }
    else if (which == 1) { oh = g_WaT_hi;  ol = g_WaT_lo;  }
    else                 { oh = g_Wc1T_hi; ol = g_Wc1T_lo; }
    __shared__ float t[32][33];
    const int k0 = blockIdx.x * 32, n0 = blockIdx.y * 32;
    const int tx = threadIdx.x, ty = threadIdx.y;
    for (int i = ty; i < 32; i += 8)
        t[i][tx] = W[(k0 + i) * EDIM + n0 + tx];
    __syncthreads();
    for (int i = ty; i < 32; i += 8)
        split_store(oh, ol, (size_t)(n0 + i) * K + k0 + tx, t[tx][i]);
}

// ---------------- fused sequence-mean reductions -> bf16 hi/lo directly -----
__global__ void reduce_kernel(const float4* __restrict__ Q,
                              const float4* __restrict__ Vq,
                              const float4* __restrict__ A,
                              const float4* __restrict__ Va,
                              const int* __restrict__ qlen,
                              const int* __restrict__ alen) {
    const int b = blockIdx.x;
    const int which = blockIdx.y;
    const int d4 = threadIdx.x;
    const int stride = BATCH * (D2 / 4);

    const float4* p;
    int L;
    if (which == 0)      { L = max(qlen[b], 1); p = Q  + b * (D2 / 4) + d4; }
    else if (which == 1) { L = TV;              p = Vq + b * (D2 / 4) + d4; }
    else if (which == 2) { L = max(alen[b], 1); p = A  + b * (D2 / 4) + d4; }
    else                 { L = TV;              p = Va + b * (D2 / 4) + d4; }

    float4 acc = make_float4(0.f, 0.f, 0.f, 0.f);
    #pragma unroll 8
    for (int t = 0; t < L; t++) {
        float4 v = p[t * stride];
        acc.x += v.x; acc.y += v.y; acc.z += v.z; acc.w += v.w;
    }
    const float inv = 1.f / (float)L;
    float vals[4] = {acc.x * inv, acc.y * inv, acc.z * inv, acc.w * inv};

    size_t base;
    __nv_bfloat16 *hi, *lo;
    if (which == 0)      { hi = g_qm_hi; lo = g_qm_lo; base = (size_t)b * D2 + 4 * d4; }
    else if (which == 1) { hi = g_X_hi;  lo = g_X_lo;  base = (size_t)b * D6 + EDIM + 4 * d4; }
    else if (which == 2) { hi = g_am_hi; lo = g_am_lo; base = (size_t)b * D2 + 4 * d4; }
    else                 { hi = g_X_hi;  lo = g_X_lo;  base = (size_t)b * D6 + 2048 + 4 * d4; }
    #pragma unroll
    for (int j = 0; j < 4; j++) split_store(hi, lo, base + j, vals[j]);
}

// ---------------- split-bf16 GEMM via mma.sync + ldmatrix -------------------
// MODE 0 (fused, BM=128, 256 thr): z=0: qm@WqT -> X[:,0:512) split-stored
//                                  z=1: am@WaT -> X[:,1536:2048) split-stored
// MODE 2 (BM=64, 128 thr): X@Wc1T + ELU -> g_h (fp32)
template <int MODE>
__global__ __launch_bounds__(MODE == 2 ? 128 : 256)
void gemm_mma(const float* __restrict__ bias0, const float* __restrict__ bias1) {
    constexpr int BM_  = (MODE == 2) ? 64 : 128;
    constexpr int NT   = (MODE == 2) ? 128 : 256;
    constexpr int NWM  = BM_ / 32;
    constexpr int AV   = BM_ * 4 / NT;       // uint4 loads per thread for A
    constexpr int BV   = 256 / NT;           // uint4 loads per thread for B
    constexpr int OA_H = 0;
    constexpr int OA_L = BM_ * ROWB;
    constexpr int OB_H = 2 * BM_ * ROWB;
    constexpr int OB_L = OB_H + 64 * ROWB;
    __shared__ __align__(16) unsigned char smem[2 * BM_ * ROWB + 2 * 64 * ROWB];

    const int tid = threadIdx.x;
    const int w = tid >> 5, l = tid & 31;
    const int wm = w % NWM, wn = w / NWM;
    const int g = l >> 2, tg = l & 3;

    const __nv_bfloat16 *Ahi, *Alo, *Bhi, *Blo;
    const float* bias;
    int Ktot, colbase;
    if (MODE == 2) {
        Ahi = g_X_hi; Alo = g_X_lo; Bhi = g_Wc1T_hi; Blo = g_Wc1T_lo;
        bias = bias0; colbase = 0; Ktot = D6;
    } else {
        if (blockIdx.z == 0) {
            Ahi = g_qm_hi; Alo = g_qm_lo; Bhi = g_WqT_hi; Blo = g_WqT_lo;
            bias = bias0; colbase = 0;
        } else {
            Ahi = g_am_hi; Alo = g_am_lo; Bhi = g_WaT_hi; Blo = g_WaT_lo;
            bias = bias1; colbase = 3 * EDIM;
        }
        Ktot = D2;
    }

    const int bm = blockIdx.y * BM_, bn = blockIdx.x * 64;
    const int ldv = Ktot >> 3;
    const uint4* gAhi = (const uint4*)Ahi + (size_t)bm * ldv;
    const uint4* gAlo = (const uint4*)Alo + (size_t)bm * ldv;
    const uint4* gBhi = (const uint4*)Bhi + (size_t)bn * ldv;
    const uint4* gBlo = (const uint4*)Blo + (size_t)bn * ldv;

    // ldmatrix lane addressing (verified against PTX fragment tables):
    // A 16x16 tile -> 4 m8n8: [rows0-7,k0-7][rows8-15,k0-7][rows0-7,k8-15][rows8-15,k8-15]
    const uint32_t S = smem_u32(smem);
    const int aRow = l & 15, aC = (l >> 4) * 16;
    const int bRow = ((l >> 4) & 1) * 8 + (l & 7), bC = ((l >> 3) & 1) * 16;
    const uint32_t aH = S + OA_H + (wm * 32 + aRow) * ROWB + aC;
    const uint32_t aL = aH + (OA_L - OA_H);
    const uint32_t bH = S + OB_H + (wn * 32 + bRow) * ROWB + bC;
    const uint32_t bL = bH + (OB_L - OB_H);

    float c[2][4][4] = {};

    const int niter = Ktot / 32;
    uint4 pAh[AV], pAl[AV], pBh[BV], pBl[BV];
    #pragma unroll
    for (int i = 0; i < AV; i++) {
        const int v = tid + i * NT, r = v >> 2, s = v & 3;
        pAh[i] = gAhi[r * ldv + s]; pAl[i] = gAlo[r * ldv + s];
    }
    #pragma unroll
    for (int i = 0; i < BV; i++) {
        const int v = tid + i * NT, r = v >> 2, s = v & 3;
        pBh[i] = gBhi[r * ldv + s]; pBl[i] = gBlo[r * ldv + s];
    }

    for (int it = 0; it < niter; it++) {
        __syncthreads();
        #pragma unroll
        for (int i = 0; i < AV; i++) {
            const int v = tid + i * NT, r = v >> 2, s = v & 3;
            *(uint4*)(smem + OA_H + r * ROWB + s * 16) = pAh[i];
            *(uint4*)(smem + OA_L + r * ROWB + s * 16) = pAl[i];
        }
        #pragma unroll
        for (int i = 0; i < BV; i++) {
            const int v = tid + i * NT, r = v >> 2, s = v & 3;
            *(uint4*)(smem + OB_H + r * ROWB + s * 16) = pBh[i];
            *(uint4*)(smem + OB_L + r * ROWB + s * 16) = pBl[i];
        }
        __syncthreads();

        if (it + 1 < niter) {
            const int kv = (it + 1) * 4;
            #pragma unroll
            for (int i = 0; i < AV; i++) {
                const int v = tid + i * NT, r = v >> 2, s = v & 3;
                pAh[i] = gAhi[r * ldv + kv + s]; pAl[i] = gAlo[r * ldv + kv + s];
            }
            #pragma unroll
            for (int i = 0; i < BV; i++) {
                const int v = tid + i * NT, r = v >> 2, s = v & 3;
                pBh[i] = gBhi[r * ldv + kv + s]; pBl[i] = gBlo[r * ldv + kv + s];
            }
        }

        #pragma unroll
        for (int ks = 0; ks < 2; ks++) {
            const int kb = ks * 32;
            uint32_t ah[2][4], al[2][4], bh[2][4], bl[2][4];
            #pragma unroll
            for (int mt = 0; mt < 2; mt++) {
                ldmat4(ah[mt], aH + mt * (16 * ROWB) + kb);
                ldmat4(al[mt], aL + mt * (16 * ROWB) + kb);
            }
            #pragma unroll
            for (int np = 0; np < 2; np++) {
                ldmat4(bh[np], bH + np * (16 * ROWB) + kb);
                ldmat4(bl[np], bL + np * (16 * ROWB) + kb);
            }
            #pragma unroll
            for (int mt = 0; mt < 2; mt++)
                #pragma unroll
                for (int np = 0; np < 2; np++)
                    #pragma unroll
                    for (int h = 0; h < 2; h++) {
                        float* acc = c[mt][np * 2 + h];
                        mma_bf16(acc, ah[mt], bh[np][h * 2], bh[np][h * 2 + 1]);
                        mma_bf16(acc, al[mt], bh[np][h * 2], bh[np][h * 2 + 1]);
                        mma_bf16(acc, ah[mt], bl[np][h * 2], bl[np][h * 2 + 1]);
                    }
        }
    }

    #pragma unroll
    for (int mt = 0; mt < 2; mt++) {
        #pragma unroll
        for (int nt = 0; nt < 4; nt++) {
            const int col = bn + wn * 32 + nt * 8 + tg * 2;
            const float b0v = bias[col], b1v = bias[col + 1];
            const int r0 = bm + wm * 32 + mt * 16 + g;
            float v00 = c[mt][nt][0] + b0v;
            float v01 = c[mt][nt][1] + b1v;
            float v10 = c[mt][nt][2] + b0v;
            float v11 = c[mt][nt][3] + b1v;
            if (MODE == 2) {
                if (v00 <= 0.f) v00 = expm1f(v00);
                if (v01 <= 0.f) v01 = expm1f(v01);
                if (v10 <= 0.f) v10 = expm1f(v10);
                if (v11 <= 0.f) v11 = expm1f(v11);
                g_h[(size_t)r0 * EDIM + col]           = v00;
                g_h[(size_t)r0 * EDIM + col + 1]       = v01;
                g_h[(size_t)(r0 + 8) * EDIM + col]     = v10;
                g_h[(size_t)(r0 + 8) * EDIM + col + 1] = v11;
            } else {
                const size_t base0 = (size_t)r0 * D6 + colbase + col;
                const size_t base1 = (size_t)(r0 + 8) * D6 + colbase + col;
                split_store(g_X_hi, g_X_lo, base0, v00);
                split_store(g_X_hi, g_X_lo, base0 + 1, v01);
                split_store(g_X_hi, g_X_lo, base1, v10);
                split_store(g_X_hi, g_X_lo, base1 + 1, v11);
            }
        }
    }
}

// ---------------- BN batch stats --------------------------------------------
__global__ void bn_stats_kernel() {
    const int r0 = blockIdx.x * 64;
    for (int c = threadIdx.x; c < EDIM; c += blockDim.x) {
        float s = 0.f, s2 = 0.f;
        #pragma unroll 8
        for (int r = 0; r < 64; r++) {
            float v = g_h[(size_t)(r0 + r) * EDIM + c];
            s += v; s2 += v * v;
        }
        atomicAdd(&g_sum[c], s);
        atomicAdd(&g_sumsq[c], s2);
    }
}

// ---------------- fold BN + Wc2 ---------------------------------------------
__global__ void bn_finalize_kernel(const float* __restrict__ gamma,
                                   const float* __restrict__ beta,
                                   const float* __restrict__ Wc2,
                                   const float* __restrict__ bc2) {
    __shared__ float red[EDIM];
    const int c = threadIdx.x;
    const float invB = 1.f / (float)BATCH;
    float mu  = g_sum[c] * invB;
    float var = fmaxf(g_sumsq[c] * invB - mu * mu, 0.f);
    float s   = gamma[c] * rsqrtf(var + BN_EPS);
    float w2  = Wc2[c];
    g_wc[c]   = s * w2;
    red[c]    = (beta[c] - mu * s) * w2;
    __syncthreads();
    for (int off = EDIM / 2; off > 0; off >>= 1) {
        if (c < off) red[c] += red[c + off];
        __syncthreads();
    }
    if (c == 0) g_cst[0] = red[0] + bc2[0];
}

// ---------------- final GEMV ------------------------------------------------
__global__ void gemv_kernel(float* __restrict__ out) {
    const int warp = threadIdx.x >> 5;
    const int lane = threadIdx.x & 31;
    const int b = blockIdx.x * 8 + warp;
    const float* hr = g_h + (size_t)b * EDIM;
    float s = 0.f;
    #pragma unroll
    for (int c = lane; c < EDIM; c += 32) s += hr[c] * g_wc[c];
    #pragma unroll
    for (int off = 16; off > 0; off >>= 1) s += __shfl_down_sync(0xffffffffu, s, off);
    if (lane == 0) out[b] = s + g_cst[0];
}

// ---------------- launcher --------------------------------------------------
extern "C" void kernel_launch(void* const* d_in, const int* in_sizes, int n_in,
                              void* d_out, int out_size) {
    const float* Q    = (const float*)d_in[0];
    const float* Vq   = (const float*)d_in[1];
    const float* Aa   = (const float*)d_in[2];
    const float* Va   = (const float*)d_in[3];
    const int*   qlen = (const int*)d_in[4];
    const int*   alen = (const int*)d_in[5];
    const float* Wq   = (const float*)d_in[6];
    const float* bq   = (const float*)d_in[7];
    const float* Wa   = (const float*)d_in[8];
    const float* ba   = (const float*)d_in[9];
    const float* Wc1  = (const float*)d_in[10];
    const float* bc1  = (const float*)d_in[11];
    const float* gam  = (const float*)d_in[12];
    const float* bet  = (const float*)d_in[13];
    const float* Wc2  = (const float*)d_in[14];
    const float* bc2  = (const float*)d_in[15];
    float* out = (float*)d_out;

    zero_stats_kernel<<<1, EDIM>>>();
    wsplit_kernel<<<dim3(D2 / 32, EDIM / 32), dim3(32, 8)>>>(Wq, 0, D2);
    wsplit_kernel<<<dim3(D2 / 32, EDIM / 32), dim3(32, 8)>>>(Wa, 1, D2);
    wsplit_kernel<<<dim3(D6 / 32, EDIM / 32), dim3(32, 8)>>>(Wc1, 2, D6);
    reduce_kernel<<<dim3(BATCH, 4), 256>>>((const float4*)Q, (const float4*)Vq,
                                           (const float4*)Aa, (const float4*)Va,
                                           qlen, alen);
    gemm_mma<0><<<dim3(EDIM / 64, BATCH / 128, 2), 256>>>(bq, ba);   // 160 CTAs
    gemm_mma<2><<<dim3(EDIM / 64, BATCH / 64), 128>>>(bc1, bc1);     // 160 CTAs
    bn_stats_kernel<<<BATCH / 64, 256>>>();
    bn_finalize_kernel<<<1, EDIM>>>(gam, bet, Wc2, bc2);
    gemv_kernel<<<BATCH / 8, 256>>>(out);
}